// round 10
// baseline (speedup 1.0000x reference)
#include <cuda_runtime.h>
#include <cuda_bf16.h>
#include <cstdint>
#include <math.h>

#define NN    4096
#define DIN   512
#define DD    128
#define NG    16
#define NPG   256
#define RSCALE 0.08838834764831843f   // 1/sqrt(128)

// ---------------- device scratch (allocation-free) ----------------
__device__ __nv_bfloat16 g_qh[NN * DD];
__device__ __nv_bfloat16 g_ql[NN * DD];
__device__ __nv_bfloat16 g_kh[NN * DD];
__device__ __nv_bfloat16 g_kl[NN * DD];
__device__ __nv_bfloat16 g_vh[NN * DD];
__device__ __nv_bfloat16 g_vl[NN * DD];
__device__ __nv_bfloat16 g_xh[NN * DIN];
__device__ __nv_bfloat16 g_xl[NN * DIN];
__device__ __nv_bfloat16 g_wh[3 * DD * DIN];
__device__ __nv_bfloat16 g_wl[3 * DD * DIN];
__device__ float g_bias[NN * NPG];   // compact block-diagonal masked bias

// ---------------- baseline-PTX tensor-core helpers ----------------
static __device__ __forceinline__ uint32_t smem_u32(const void* p) {
    uint32_t a;
    asm("{ .reg .u64 t; cvta.to.shared.u64 t, %1; cvt.u32.u64 %0, t; }" : "=r"(a) : "l"(p));
    return a;
}
static __device__ __forceinline__ void ldsm_x4(uint32_t addr, uint32_t* r) {
    asm volatile("ldmatrix.sync.aligned.m8n8.x4.shared.b16 {%0,%1,%2,%3}, [%4];"
                 : "=r"(r[0]), "=r"(r[1]), "=r"(r[2]), "=r"(r[3]) : "r"(addr));
}
static __device__ __forceinline__ void ldsm_x4_t(uint32_t addr, uint32_t* r) {
    asm volatile("ldmatrix.sync.aligned.m8n8.x4.trans.shared.b16 {%0,%1,%2,%3}, [%4];"
                 : "=r"(r[0]), "=r"(r[1]), "=r"(r[2]), "=r"(r[3]) : "r"(addr));
}
static __device__ __forceinline__ void mma_bf16(float* c, const uint32_t* a, const uint32_t* b) {
    asm volatile(
        "mma.sync.aligned.m16n8k16.row.col.f32.bf16.bf16.f32 "
        "{%0,%1,%2,%3}, {%4,%5,%6,%7}, {%8,%9}, {%0,%1,%2,%3};"
        : "+f"(c[0]), "+f"(c[1]), "+f"(c[2]), "+f"(c[3])
        : "r"(a[0]), "r"(a[1]), "r"(a[2]), "r"(a[3]), "r"(b[0]), "r"(b[1]));
}
static __device__ __forceinline__ uint32_t split_pack(float a, float b, uint32_t* lo) {
    __nv_bfloat16 ha = __float2bfloat16(a), hb = __float2bfloat16(b);
    __nv_bfloat16 la = __float2bfloat16(a - __bfloat162float(ha));
    __nv_bfloat16 lb = __float2bfloat16(b - __bfloat162float(hb));
    *lo = (uint32_t)__bfloat16_as_ushort(la) | ((uint32_t)__bfloat16_as_ushort(lb) << 16);
    return (uint32_t)__bfloat16_as_ushort(ha) | ((uint32_t)__bfloat16_as_ushort(hb) << 16);
}

// =====================================================================
// Kernel P: compact masked bias  g_bias[n][j] = keep ? b+c : -1e30
// =====================================================================
__global__ void __launch_bounds__(256) prep_bias_kernel(
    const float* __restrict__ b, const float* __restrict__ c, const int* __restrict__ mask)
{
    int i = blockIdx.x * 256 + threadIdx.x;   // float4 index over [NN*NPG/4]
    int e = i * 4;
    int row = e >> 8;                 // 256 cols per row
    int col = e & 255;
    int kb  = (row >> 8) << 8;        // graph key base
    size_t idx = (size_t)row * NN + kb + col;
    float4 bv = *(const float4*)(b + idx);
    float4 cv = *(const float4*)(c + idx);
    int4   mv = *(const int4*)(mask + idx);
    float4 o;
    o.x = mv.x ? bv.x + cv.x : -1e30f;
    o.y = mv.y ? bv.y + cv.y : -1e30f;
    o.z = mv.z ? bv.z + cv.z : -1e30f;
    o.w = mv.w ? bv.w + cv.w : -1e30f;
    *(float4*)(g_bias + e) = o;
}

// =====================================================================
// Kernel 0a: split-convert x -> (xh, xl) bf16
// =====================================================================
__global__ void __launch_bounds__(256) convert_x_kernel(const float* __restrict__ x)
{
    int i = blockIdx.x * 256 + threadIdx.x;
    float4 v = ((const float4*)x)[i];
    uint2 hp, lp;
    hp.x = split_pack(v.x, v.y, &lp.x);
    hp.y = split_pack(v.z, v.w, &lp.y);
    ((uint2*)g_xh)[i] = hp;
    ((uint2*)g_xl)[i] = lp;
}

// =====================================================================
// Kernel 0b: split-convert Wq|Wk|Wv -> (g_wh, g_wl) [384, 512]
// =====================================================================
__global__ void __launch_bounds__(256) convert_w_kernel(
    const float* __restrict__ Wq, const float* __restrict__ Wk, const float* __restrict__ Wv)
{
    int i = blockIdx.x * 256 + threadIdx.x;
    int fidx = i * 4;
    int row = fidx >> 9;
    int col = fidx & 511;
    const float* src = (row < 128) ? (Wq + row * 512)
                     : (row < 256) ? (Wk + (row - 128) * 512)
                                   : (Wv + (row - 256) * 512);
    float4 v = *(const float4*)(src + col);
    uint2 hp, lp;
    hp.x = split_pack(v.x, v.y, &lp.x);
    hp.y = split_pack(v.z, v.w, &lp.y);
    ((uint2*)g_wh)[i] = hp;
    ((uint2*)g_wl)[i] = lp;
}

// =====================================================================
// Kernel 1: QKV projection via mma.sync (bf16 split, 3 accumulating passes)
// grid (128, 3), block 128. Stores split-bf16 q/k/v.
// =====================================================================
__global__ void __launch_bounds__(128) qkv_mma_kernel(
    const float* __restrict__ bq, const float* __restrict__ bk, const float* __restrict__ bv)
{
    __shared__ __align__(16) __nv_bfloat16 sAh[32 * 72];
    __shared__ __align__(16) __nv_bfloat16 sAl[32 * 72];
    __shared__ __align__(16) __nv_bfloat16 sBh[128 * 72];
    __shared__ __align__(16) __nv_bfloat16 sBl[128 * 72];

    const int t    = threadIdx.x;
    const int lane = t & 31;
    const int wid  = t >> 5;
    const int m0   = blockIdx.x * 32;
    const int z    = blockIdx.y;

    const __nv_bfloat16* Wh = g_wh + z * DD * DIN;
    const __nv_bfloat16* Wl = g_wl + z * DD * DIN;
    const float* bias = (z == 0) ? bq : ((z == 1) ? bk : bv);
    __nv_bfloat16* outh = (z == 0) ? g_qh : ((z == 1) ? g_kh : g_vh);
    __nv_bfloat16* outl = (z == 0) ? g_ql : ((z == 1) ? g_kl : g_vl);

    const int wm = wid & 1;
    const int wn = wid >> 1;

    float acc[8][4];
#pragma unroll
    for (int nt = 0; nt < 8; nt++)
#pragma unroll
        for (int j = 0; j < 4; j++) acc[nt][j] = 0.f;

    const uint32_t aoff = (uint32_t)(((wm * 16 + (lane & 15)) * 72 + ((lane >> 4) * 8)) * 2);
    const uint32_t aAh = smem_u32(sAh) + aoff;
    const uint32_t aAl = smem_u32(sAl) + aoff;
    const uint32_t boff = (uint32_t)((((lane & 7)) * 72 + ((lane >> 3) * 8)) * 2);
    const uint32_t aBh = smem_u32(sBh) + boff;
    const uint32_t aBl = smem_u32(sBl) + boff;

    for (int ch = 0; ch < 8; ch++) {
        __syncthreads();
#pragma unroll
        for (int j = 0; j < 2; j++) {
            int c   = t + j * 128;
            int row = c >> 3, o8 = (c & 7) * 8;
            int gsrc = (m0 + row) * DIN + ch * 64 + o8;
            *(uint4*)(sAh + row * 72 + o8) = *(const uint4*)(g_xh + gsrc);
            *(uint4*)(sAl + row * 72 + o8) = *(const uint4*)(g_xl + gsrc);
        }
#pragma unroll
        for (int j = 0; j < 8; j++) {
            int c   = t + j * 128;
            int row = c >> 3, o8 = (c & 7) * 8;
            int gsrc = row * DIN + ch * 64 + o8;
            *(uint4*)(sBh + row * 72 + o8) = *(const uint4*)(Wh + gsrc);
            *(uint4*)(sBl + row * 72 + o8) = *(const uint4*)(Wl + gsrc);
        }
        __syncthreads();

        uint32_t ah[4][4], al[4][4];
#pragma unroll
        for (int ks = 0; ks < 4; ks++) {
            ldsm_x4(aAh + ks * 32, ah[ks]);
            ldsm_x4(aAl + ks * 32, al[ks]);
        }

#pragma unroll
        for (int nt = 0; nt < 8; nt++) {
            uint32_t bofs = (uint32_t)((wn * 64 + nt * 8) * 144);
#pragma unroll
            for (int kp = 0; kp < 2; kp++) {
                uint32_t bh[4], bl[4];
                ldsm_x4(aBh + bofs + kp * 64, bh);
                ldsm_x4(aBl + bofs + kp * 64, bl);
                mma_bf16(acc[nt], ah[kp * 2],     bh);
                mma_bf16(acc[nt], ah[kp * 2],     bl);
                mma_bf16(acc[nt], al[kp * 2],     bh);
                mma_bf16(acc[nt], ah[kp * 2 + 1], bh + 2);
                mma_bf16(acc[nt], ah[kp * 2 + 1], bl + 2);
                mma_bf16(acc[nt], al[kp * 2 + 1], bh + 2);
            }
        }
    }

    const int gr = lane >> 2;
    const int tq = lane & 3;
    const int row = m0 + wm * 16 + gr;
#pragma unroll
    for (int nt = 0; nt < 8; nt++) {
        int col = wn * 64 + nt * 8 + tq * 2;
        float2 bz = *(const float2*)(bias + col);
        uint32_t lo0, lo1;
        uint32_t hi0 = split_pack(acc[nt][0] + bz.x, acc[nt][1] + bz.y, &lo0);
        uint32_t hi1 = split_pack(acc[nt][2] + bz.x, acc[nt][3] + bz.y, &lo1);
        *(uint32_t*)(outh + row * DD + col)       = hi0;
        *(uint32_t*)(outl + row * DD + col)       = lo0;
        *(uint32_t*)(outh + (row + 8) * DD + col) = hi1;
        *(uint32_t*)(outl + (row + 8) * DD + col) = lo1;
    }
}

// =====================================================================
// Kernel 2: block-diagonal attention on tensor cores.
// grid (16, 16): x = 16-row tile, y = graph. block 128 (4 warps, col-split).
// S kept in registers; softmax fused with precomputed g_bias; P via smem.
// =====================================================================
#define QSTR 136
#define KSTR 136
#define PSTR 264

#define OFF_QH 0
#define OFF_QL (OFF_QH + 16 * QSTR)
#define OFF_KH (OFF_QL + 16 * QSTR)
#define OFF_KL (OFF_KH + 64 * KSTR)
#define OFF_PH (OFF_KL + 64 * KSTR)
#define OFF_PL (OFF_PH + 16 * PSTR)
#define OFF_END (OFF_PL + 16 * PSTR)
// floats after bf16 region
#define ATTN_SMEM (OFF_END * 2 + (64 + 64) * 4)

__global__ void __launch_bounds__(128) attn_mma_kernel(float* __restrict__ out)
{
    extern __shared__ char smbase[];
    __nv_bfloat16* sQh = (__nv_bfloat16*)smbase;
    __nv_bfloat16* sKh = (__nv_bfloat16*)smbase + OFF_KH;
    __nv_bfloat16* sKl = (__nv_bfloat16*)smbase + OFF_KL;
    __nv_bfloat16* sPh = (__nv_bfloat16*)smbase + OFF_PH;
    __nv_bfloat16* sPl = (__nv_bfloat16*)smbase + OFF_PL;
    float* sMax = (float*)(smbase + OFF_END * 2);        // [16][4]
    float* sSum = sMax + 64;                              // [16][4]

    const int t    = threadIdx.x;
    const int lane = t & 31;
    const int wn   = t >> 5;       // 0..3 (column split)
    const int g    = blockIdx.y;
    const int nbase = g * NPG + blockIdx.x * 16;
    const int kbase = g * NPG;

    // ---- load Q tile [16][128] hi/lo ----
    {
        int row = t >> 3, c0 = (t & 7) * 16;
#pragma unroll
        for (int i = 0; i < 2; i++) {
            *(uint4*)(sQh + OFF_QL - OFF_QH + row * QSTR + c0 + i * 8) =
                *(const uint4*)(g_ql + (nbase + row) * DD + c0 + i * 8);
            *(uint4*)(sQh + row * QSTR + c0 + i * 8) =
                *(const uint4*)(g_qh + (nbase + row) * DD + c0 + i * 8);
        }
    }

    const uint32_t aQh = smem_u32(sQh) +
        (uint32_t)(((lane & 15) * QSTR + (lane >> 4) * 8) * 2);
    const uint32_t aQl = aQh + 16 * QSTR * 2;
    const uint32_t bKh = smem_u32(sKh) +
        (uint32_t)(((lane & 7) * KSTR + (lane >> 3) * 8) * 2);
    const uint32_t bKl = bKh + 64 * KSTR * 2;

    const int gr = lane >> 2;
    const int tq = lane & 3;

    // ---- Phase 1: S = Q K^T, registers only ----
    float s[8][4];
#pragma unroll
    for (int ti = 0; ti < 8; ti++)
#pragma unroll
        for (int j = 0; j < 4; j++) s[ti][j] = 0.f;

    for (int ch = 0; ch < 4; ch++) {
        __syncthreads();
        {
            int row = t >> 1, c0 = (t & 1) * 64;
#pragma unroll
            for (int i = 0; i < 8; i++) {
                *(uint4*)(sKh + row * KSTR + c0 + i * 8) =
                    *(const uint4*)(g_kh + (kbase + ch * 64 + row) * DD + c0 + i * 8);
                *(uint4*)(sKl + row * KSTR + c0 + i * 8) =
                    *(const uint4*)(g_kl + (kbase + ch * 64 + row) * DD + c0 + i * 8);
            }
        }
        __syncthreads();

#pragma unroll
        for (int kp = 0; kp < 4; kp++) {
            uint32_t ah0[4], ah1[4], al0[4], al1[4];
            ldsm_x4(aQh + kp * 64,      ah0);
            ldsm_x4(aQh + kp * 64 + 32, ah1);
            ldsm_x4(aQl + kp * 64,      al0);
            ldsm_x4(aQl + kp * 64 + 32, al1);
#pragma unroll
            for (int nt = 0; nt < 2; nt++) {
                int ti = ch * 2 + nt;
                uint32_t bofs = (uint32_t)(((wn * 16 + nt * 8) * KSTR) * 2) + kp * 64;
                uint32_t bh[4], bl[4];
                ldsm_x4(bKh + bofs, bh);
                ldsm_x4(bKl + bofs, bl);
                mma_bf16(s[ti], ah0, bh);
                mma_bf16(s[ti], ah0, bl);
                mma_bf16(s[ti], al0, bh);
                mma_bf16(s[ti], ah1, bh + 2);
                mma_bf16(s[ti], ah1, bl + 2);
                mma_bf16(s[ti], al1, bh + 2);
            }
        }
    }

    // ---- bias add + row max (registers + quad shuffle + cross-warp smem) ----
    float mx0 = -1e30f, mx1 = -1e30f;
#pragma unroll
    for (int ti = 0; ti < 8; ti++) {
        int col = (ti >> 1) * 64 + wn * 16 + (ti & 1) * 8 + tq * 2;
        float2 b0 = *(const float2*)(g_bias + (nbase + gr) * NPG + col);
        float2 b1 = *(const float2*)(g_bias + (nbase + gr + 8) * NPG + col);
        s[ti][0] = s[ti][0] * RSCALE + b0.x;
        s[ti][1] = s[ti][1] * RSCALE + b0.y;
        s[ti][2] = s[ti][2] * RSCALE + b1.x;
        s[ti][3] = s[ti][3] * RSCALE + b1.y;
        mx0 = fmaxf(mx0, fmaxf(s[ti][0], s[ti][1]));
        mx1 = fmaxf(mx1, fmaxf(s[ti][2], s[ti][3]));
    }
    mx0 = fmaxf(mx0, __shfl_xor_sync(0xffffffffu, mx0, 1));
    mx0 = fmaxf(mx0, __shfl_xor_sync(0xffffffffu, mx0, 2));
    mx1 = fmaxf(mx1, __shfl_xor_sync(0xffffffffu, mx1, 1));
    mx1 = fmaxf(mx1, __shfl_xor_sync(0xffffffffu, mx1, 2));
    if (tq == 0) {
        sMax[gr * 4 + wn]       = mx0;
        sMax[(gr + 8) * 4 + wn] = mx1;
    }
    __syncthreads();
    mx0 = fmaxf(fmaxf(sMax[gr * 4 + 0], sMax[gr * 4 + 1]),
                fmaxf(sMax[gr * 4 + 2], sMax[gr * 4 + 3]));
    mx1 = fmaxf(fmaxf(sMax[(gr + 8) * 4 + 0], sMax[(gr + 8) * 4 + 1]),
                fmaxf(sMax[(gr + 8) * 4 + 2], sMax[(gr + 8) * 4 + 3]));

    // ---- exp + sum; P -> smem split-bf16 ----
    float sum0 = 0.f, sum1 = 0.f;
#pragma unroll
    for (int ti = 0; ti < 8; ti++) {
        int col = (ti >> 1) * 64 + wn * 16 + (ti & 1) * 8 + tq * 2;
        float e0 = __expf(s[ti][0] - mx0);
        float e1 = __expf(s[ti][1] - mx0);
        float e2 = __expf(s[ti][2] - mx1);
        float e3 = __expf(s[ti][3] - mx1);
        sum0 += e0 + e1;
        sum1 += e2 + e3;
        uint32_t lo0, lo1;
        uint32_t hi0 = split_pack(e0, e1, &lo0);
        uint32_t hi1 = split_pack(e2, e3, &lo1);
        *(uint32_t*)(sPh + gr * PSTR + col)       = hi0;
        *(uint32_t*)(sPl + gr * PSTR + col)       = lo0;
        *(uint32_t*)(sPh + (gr + 8) * PSTR + col) = hi1;
        *(uint32_t*)(sPl + (gr + 8) * PSTR + col) = lo1;
    }
    sum0 += __shfl_xor_sync(0xffffffffu, sum0, 1);
    sum0 += __shfl_xor_sync(0xffffffffu, sum0, 2);
    sum1 += __shfl_xor_sync(0xffffffffu, sum1, 1);
    sum1 += __shfl_xor_sync(0xffffffffu, sum1, 2);
    if (tq == 0) {
        sSum[gr * 4 + wn]       = sum0;
        sSum[(gr + 8) * 4 + wn] = sum1;
    }

    // ---- Phase 2: O = P V ----
    float o[4][4];
#pragma unroll
    for (int nt = 0; nt < 4; nt++)
#pragma unroll
        for (int j = 0; j < 4; j++) o[nt][j] = 0.f;

    const uint32_t aPh = smem_u32(sPh) +
        (uint32_t)(((lane & 15) * PSTR + (lane >> 4) * 8) * 2);
    const uint32_t aPl = aPh + 16 * PSTR * 2;
    const uint32_t bVh = smem_u32(sKh) +
        (uint32_t)((((lane & 7) + (lane & 8)) * KSTR + ((lane >> 4) & 1) * 8) * 2);
    const uint32_t bVl = bVh + 64 * KSTR * 2;

    for (int ch = 0; ch < 4; ch++) {
        __syncthreads();   // P writes done (ch=0) / previous V reads done
        {
            int row = t >> 1, c0 = (t & 1) * 64;
#pragma unroll
            for (int i = 0; i < 8; i++) {
                *(uint4*)(sKh + row * KSTR + c0 + i * 8) =
                    *(const uint4*)(g_vh + (kbase + ch * 64 + row) * DD + c0 + i * 8);
                *(uint4*)(sKl + row * KSTR + c0 + i * 8) =
                    *(const uint4*)(g_vl + (kbase + ch * 64 + row) * DD + c0 + i * 8);
            }
        }
        __syncthreads();

#pragma unroll
        for (int kt = 0; kt < 4; kt++) {
            uint32_t ph[4], pl[4];
            ldsm_x4(aPh + (ch * 64 + kt * 16) * 2, ph);
            ldsm_x4(aPl + (ch * 64 + kt * 16) * 2, pl);
#pragma unroll
            for (int np = 0; np < 2; np++) {
                uint32_t vofs = (uint32_t)((kt * 16 * KSTR + wn * 32 + np * 16) * 2);
                uint32_t vh[4], vl[4];
                ldsm_x4_t(bVh + vofs, vh);
                ldsm_x4_t(bVl + vofs, vl);
                mma_bf16(o[np * 2],     ph, vh);
                mma_bf16(o[np * 2],     ph, vl);
                mma_bf16(o[np * 2],     pl, vh);
                mma_bf16(o[np * 2 + 1], ph, vh + 2);
                mma_bf16(o[np * 2 + 1], ph, vl + 2);
                mma_bf16(o[np * 2 + 1], pl, vh + 2);
            }
        }
    }

    // ---- epilogue: normalize, store ----
    float r0inv = 1.0f / (sSum[gr * 4 + 0] + sSum[gr * 4 + 1] +
                          sSum[gr * 4 + 2] + sSum[gr * 4 + 3]);
    float r1inv = 1.0f / (sSum[(gr + 8) * 4 + 0] + sSum[(gr + 8) * 4 + 1] +
                          sSum[(gr + 8) * 4 + 2] + sSum[(gr + 8) * 4 + 3]);
    int row0 = nbase + gr;
#pragma unroll
    for (int nt = 0; nt < 4; nt++) {
        int col = wn * 32 + nt * 8 + tq * 2;
        *(float2*)(out + row0 * DD + col) =
            make_float2(o[nt][0] * r0inv, o[nt][1] * r0inv);
        *(float2*)(out + (row0 + 8) * DD + col) =
            make_float2(o[nt][2] * r1inv, o[nt][3] * r1inv);
    }
}

// =====================================================================
extern "C" void kernel_launch(void* const* d_in, const int* in_sizes, int n_in,
                              void* d_out, int out_size)
{
    const float* x    = (const float*)d_in[0];
    const float* bmat = (const float*)d_in[1];
    const float* cmat = (const float*)d_in[2];
    // d_in[3] = ptr (uniform graph layout: NPG = 256; unused)
    const int*   mask = (const int*)d_in[4];
    const float* Wq   = (const float*)d_in[5];
    const float* bq   = (const float*)d_in[6];
    const float* Wk   = (const float*)d_in[7];
    const float* bk   = (const float*)d_in[8];
    const float* Wv   = (const float*)d_in[9];
    const float* bv   = (const float*)d_in[10];
    float* out = (float*)d_out;

    cudaFuncSetAttribute(attn_mma_kernel, cudaFuncAttributeMaxDynamicSharedMemorySize,
                         ATTN_SMEM);

    prep_bias_kernel<<<(NN * NPG / 4) / 256, 256>>>(bmat, cmat, mask);
    convert_x_kernel<<<(NN * DIN / 4) / 256, 256>>>(x);
    convert_w_kernel<<<(3 * DD * DIN / 4) / 256, 256>>>(Wq, Wk, Wv);
    qkv_mma_kernel<<<dim3(128, 3), 128>>>(bq, bk, bv);
    attn_mma_kernel<<<dim3(16, 16), 128, ATTN_SMEM>>>(out);
}

// round 13
// speedup vs baseline: 1.0235x; 1.0235x over previous
#include <cuda_runtime.h>
#include <cuda_bf16.h>
#include <cstdint>
#include <math.h>

#define NN    4096
#define DIN   512
#define DD    128
#define NG    16
#define NPG   256
#define RSCALE 0.08838834764831843f   // 1/sqrt(128)

// ---------------- device scratch (allocation-free) ----------------
__device__ __nv_bfloat16 g_qh[NN * DD];
__device__ __nv_bfloat16 g_ql[NN * DD];
__device__ __nv_bfloat16 g_kh[NN * DD];
__device__ __nv_bfloat16 g_kl[NN * DD];
__device__ __nv_bfloat16 g_vh[NN * DD];
__device__ __nv_bfloat16 g_vl[NN * DD];
__device__ __nv_bfloat16 g_xh[NN * DIN];
__device__ __nv_bfloat16 g_xl[NN * DIN];
__device__ __nv_bfloat16 g_wh[3 * DD * DIN];
__device__ __nv_bfloat16 g_wl[3 * DD * DIN];
__device__ float g_bias[NN * NPG];   // compact block-diagonal masked bias

// ---------------- helpers ----------------
static __device__ __forceinline__ uint32_t smem_u32(const void* p) {
    uint32_t a;
    asm("{ .reg .u64 t; cvta.to.shared.u64 t, %1; cvt.u32.u64 %0, t; }" : "=r"(a) : "l"(p));
    return a;
}
static __device__ __forceinline__ void ldsm_x4(uint32_t addr, uint32_t* r) {
    asm volatile("ldmatrix.sync.aligned.m8n8.x4.shared.b16 {%0,%1,%2,%3}, [%4];"
                 : "=r"(r[0]), "=r"(r[1]), "=r"(r[2]), "=r"(r[3]) : "r"(addr));
}
static __device__ __forceinline__ void ldsm_x4_t(uint32_t addr, uint32_t* r) {
    asm volatile("ldmatrix.sync.aligned.m8n8.x4.trans.shared.b16 {%0,%1,%2,%3}, [%4];"
                 : "=r"(r[0]), "=r"(r[1]), "=r"(r[2]), "=r"(r[3]) : "r"(addr));
}
static __device__ __forceinline__ void mma_bf16(float* c, const uint32_t* a, const uint32_t* b) {
    asm volatile(
        "mma.sync.aligned.m16n8k16.row.col.f32.bf16.bf16.f32 "
        "{%0,%1,%2,%3}, {%4,%5,%6,%7}, {%8,%9}, {%0,%1,%2,%3};"
        : "+f"(c[0]), "+f"(c[1]), "+f"(c[2]), "+f"(c[3])
        : "r"(a[0]), "r"(a[1]), "r"(a[2]), "r"(a[3]), "r"(b[0]), "r"(b[1]));
}
static __device__ __forceinline__ uint32_t split_pack(float a, float b, uint32_t* lo) {
    __nv_bfloat16 ha = __float2bfloat16(a), hb = __float2bfloat16(b);
    __nv_bfloat16 la = __float2bfloat16(a - __bfloat162float(ha));
    __nv_bfloat16 lb = __float2bfloat16(b - __bfloat162float(hb));
    *lo = (uint32_t)__bfloat16_as_ushort(la) | ((uint32_t)__bfloat16_as_ushort(lb) << 16);
    return (uint32_t)__bfloat16_as_ushort(ha) | ((uint32_t)__bfloat16_as_ushort(hb) << 16);
}
#define CPA16(dst, src) \
    asm volatile("cp.async.cg.shared.global [%0], [%1], 16;" :: "r"(dst), "l"(src))
#define CP_COMMIT() asm volatile("cp.async.commit_group;" ::: "memory")
#define CP_WAIT0()  asm volatile("cp.async.wait_group 0;" ::: "memory")
#define CP_WAIT1()  asm volatile("cp.async.wait_group 1;" ::: "memory")

// =====================================================================
// Kernel P: compact masked bias  g_bias[n][j] = keep ? b+c : -1e30
// =====================================================================
__global__ void __launch_bounds__(256) prep_bias_kernel(
    const float* __restrict__ b, const float* __restrict__ c, const int* __restrict__ mask)
{
    int i = blockIdx.x * 256 + threadIdx.x;
    int e = i * 4;
    int row = e >> 8;
    int col = e & 255;
    int kb  = (row >> 8) << 8;
    size_t idx = (size_t)row * NN + kb + col;
    float4 bv = *(const float4*)(b + idx);
    float4 cv = *(const float4*)(c + idx);
    int4   mv = *(const int4*)(mask + idx);
    float4 o;
    o.x = mv.x ? bv.x + cv.x : -1e30f;
    o.y = mv.y ? bv.y + cv.y : -1e30f;
    o.z = mv.z ? bv.z + cv.z : -1e30f;
    o.w = mv.w ? bv.w + cv.w : -1e30f;
    *(float4*)(g_bias + e) = o;
}

// =====================================================================
// Kernel 0a/0b: split converts
// =====================================================================
__global__ void __launch_bounds__(256) convert_x_kernel(const float* __restrict__ x)
{
    int i = blockIdx.x * 256 + threadIdx.x;
    float4 v = ((const float4*)x)[i];
    uint2 hp, lp;
    hp.x = split_pack(v.x, v.y, &lp.x);
    hp.y = split_pack(v.z, v.w, &lp.y);
    ((uint2*)g_xh)[i] = hp;
    ((uint2*)g_xl)[i] = lp;
}
__global__ void __launch_bounds__(256) convert_w_kernel(
    const float* __restrict__ Wq, const float* __restrict__ Wk, const float* __restrict__ Wv)
{
    int i = blockIdx.x * 256 + threadIdx.x;
    int fidx = i * 4;
    int row = fidx >> 9;
    int col = fidx & 511;
    const float* src = (row < 128) ? (Wq + row * 512)
                     : (row < 256) ? (Wk + (row - 128) * 512)
                                   : (Wv + (row - 256) * 512);
    float4 v = *(const float4*)(src + col);
    uint2 hp, lp;
    hp.x = split_pack(v.x, v.y, &lp.x);
    hp.y = split_pack(v.z, v.w, &lp.y);
    ((uint2*)g_wh)[i] = hp;
    ((uint2*)g_wl)[i] = lp;
}

// =====================================================================
// Kernel 1: QKV projection, cp.async 2-stage pipelined mma.sync.
// grid (128, 3), block 128. Dynamic smem 90KB (2 stages).
// layout (bf16 elems): A: s*4608 + p*2304 ; B: 9216 + s*18432 + p*9216
// =====================================================================
#define QKV_SMEM_BYTES (46080 * 2)

__global__ void __launch_bounds__(128) qkv_mma_kernel(
    const float* __restrict__ bq, const float* __restrict__ bk, const float* __restrict__ bv)
{
    extern __shared__ __nv_bfloat16 dsm[];
    const uint32_t sb = smem_u32(dsm);

    const int t    = threadIdx.x;
    const int lane = t & 31;
    const int wid  = t >> 5;
    const int m0   = blockIdx.x * 32;
    const int z    = blockIdx.y;

    const __nv_bfloat16* Wh = g_wh + z * DD * DIN;
    const __nv_bfloat16* Wl = g_wl + z * DD * DIN;
    const float* bias = (z == 0) ? bq : ((z == 1) ? bk : bv);
    __nv_bfloat16* outh = (z == 0) ? g_qh : ((z == 1) ? g_kh : g_vh);
    __nv_bfloat16* outl = (z == 0) ? g_ql : ((z == 1) ? g_kl : g_vl);

    const int wm = wid & 1;
    const int wn = wid >> 1;

    auto preload = [&](int ch, int s) {
        uint32_t aBase = sb + (uint32_t)(s * 4608) * 2;
        uint32_t bBase = sb + (uint32_t)(9216 + s * 18432) * 2;
#pragma unroll
        for (int j = 0; j < 2; j++) {
            int c = t + j * 128, row = c >> 3, o8 = (c & 7) * 8;
            uint32_t d = aBase + (uint32_t)(row * 72 + o8) * 2;
            const int gsrc = (m0 + row) * DIN + ch * 64 + o8;
            CPA16(d,        g_xh + gsrc);
            CPA16(d + 4608, g_xl + gsrc);
        }
#pragma unroll
        for (int j = 0; j < 8; j++) {
            int c = t + j * 128, row = c >> 3, o8 = (c & 7) * 8;
            uint32_t d = bBase + (uint32_t)(row * 72 + o8) * 2;
            const int gsrc = row * DIN + ch * 64 + o8;
            CPA16(d,         Wh + gsrc);
            CPA16(d + 18432, Wl + gsrc);
        }
    };

    float acc[8][4];
#pragma unroll
    for (int nt = 0; nt < 8; nt++)
#pragma unroll
        for (int j = 0; j < 4; j++) acc[nt][j] = 0.f;

    const uint32_t aoff = (uint32_t)(((wm * 16 + (lane & 15)) * 72 + ((lane >> 4) * 8)) * 2);
    const uint32_t boff = (uint32_t)((((lane & 7)) * 72 + ((lane >> 3) * 8)) * 2);

    preload(0, 0); CP_COMMIT();
    preload(1, 1); CP_COMMIT();

    for (int ch = 0; ch < 8; ch++) {
        if (ch == 7) { CP_WAIT0(); } else { CP_WAIT1(); }
        __syncthreads();

        const int s = ch & 1;
        const uint32_t aAh = sb + (uint32_t)(s * 4608) * 2 + aoff;
        const uint32_t aAl = aAh + 4608;
        const uint32_t aBh = sb + (uint32_t)(9216 + s * 18432) * 2 + boff;
        const uint32_t aBl = aBh + 18432;

        uint32_t ah[4][4], al[4][4];
#pragma unroll
        for (int ks = 0; ks < 4; ks++) {
            ldsm_x4(aAh + ks * 32, ah[ks]);
            ldsm_x4(aAl + ks * 32, al[ks]);
        }
#pragma unroll
        for (int nt = 0; nt < 8; nt++) {
            uint32_t bofs = (uint32_t)((wn * 64 + nt * 8) * 144);
#pragma unroll
            for (int kp = 0; kp < 2; kp++) {
                uint32_t bh[4], bl[4];
                ldsm_x4(aBh + bofs + kp * 64, bh);
                ldsm_x4(aBl + bofs + kp * 64, bl);
                mma_bf16(acc[nt], ah[kp * 2],     bh);
                mma_bf16(acc[nt], ah[kp * 2],     bl);
                mma_bf16(acc[nt], al[kp * 2],     bh);
                mma_bf16(acc[nt], ah[kp * 2 + 1], bh + 2);
                mma_bf16(acc[nt], ah[kp * 2 + 1], bl + 2);
                mma_bf16(acc[nt], al[kp * 2 + 1], bh + 2);
            }
        }
        __syncthreads();
        if (ch + 2 < 8) { preload(ch + 2, s); CP_COMMIT(); }
    }

    const int gr = lane >> 2;
    const int tq = lane & 3;
    const int row = m0 + wm * 16 + gr;
#pragma unroll
    for (int nt = 0; nt < 8; nt++) {
        int col = wn * 64 + nt * 8 + tq * 2;
        float2 bz = *(const float2*)(bias + col);
        uint32_t lo0, lo1;
        uint32_t hi0 = split_pack(acc[nt][0] + bz.x, acc[nt][1] + bz.y, &lo0);
        uint32_t hi1 = split_pack(acc[nt][2] + bz.x, acc[nt][3] + bz.y, &lo1);
        *(uint32_t*)(outh + row * DD + col)       = hi0;
        *(uint32_t*)(outl + row * DD + col)       = lo0;
        *(uint32_t*)(outh + (row + 8) * DD + col) = hi1;
        *(uint32_t*)(outl + (row + 8) * DD + col) = lo1;
    }
}

// =====================================================================
// Kernel 2: block-diagonal attention, cp.async 2-stage pipelined.
// grid (16, 16), block 128 (4 warps col-split). Dynamic smem ~110KB.
// bf16-elem layout:
//   Q  hi 0 / lo 2176                              (total 4352)
//   KV base 4352, stage stride 17408, part 8704    (total 34816)
//   P  base 39168 hi / 43392 lo                    (total 8448) -> end 47616
// byte layout after bf16 region (95232B):
//   bias float[16][260] @95232 ; sMax @111872 ; sSum @112128 ; total 112384
// =====================================================================
#define ATTN_SMEM 112384

__global__ void __launch_bounds__(128) attn_mma_kernel(float* __restrict__ out)
{
    extern __shared__ __nv_bfloat16 dsm[];
    const uint32_t sb = smem_u32(dsm);
    __nv_bfloat16* sPh = dsm + 39168;
    __nv_bfloat16* sPl = dsm + 43392;
    float* sBiasF = (float*)((char*)dsm + 95232);
    float* sMax   = (float*)((char*)dsm + 111872);
    float* sSum   = sMax + 64;

    const int t    = threadIdx.x;
    const int lane = t & 31;
    const int wn   = t >> 5;
    const int g    = blockIdx.y;
    const int nbase = g * NPG + blockIdx.x * 16;
    const int kbase = g * NPG;

    auto cpKV = [&](const __nv_bfloat16* srcH, const __nv_bfloat16* srcL, int ch, int s) {
        uint32_t base = sb + (uint32_t)(4352 + s * 17408) * 2;
        int row = t >> 1, c0 = (t & 1) * 64;
        const int gsrc = (kbase + ch * 64 + row) * DD + c0;
#pragma unroll
        for (int i = 0; i < 8; i++) {
            uint32_t d = base + (uint32_t)(row * 136 + c0 + i * 8) * 2;
            CPA16(d,         srcH + gsrc + i * 8);
            CPA16(d + 17408, srcL + gsrc + i * 8);
        }
    };

    // ---- group 1: Q + bias + K0 ; group 2: K1 ----
    {
        int row = t >> 3, c0 = (t & 7) * 16;
        const int gsrc = (nbase + row) * DD + c0;
#pragma unroll
        for (int i = 0; i < 2; i++) {
            uint32_t d = sb + (uint32_t)(row * 136 + c0 + i * 8) * 2;
            CPA16(d,        g_qh + gsrc + i * 8);
            CPA16(d + 4352, g_ql + gsrc + i * 8);
        }
        int bcol = (t & 7) * 32;
        const float* bsrc = g_bias + (nbase + row) * NPG + bcol;
        uint32_t bdst = sb + 95232 + (uint32_t)(row * 260 + bcol) * 4;
#pragma unroll
        for (int i = 0; i < 8; i++)
            CPA16(bdst + i * 16, bsrc + i * 4);
    }
    cpKV(g_kh, g_kl, 0, 0); CP_COMMIT();
    cpKV(g_kh, g_kl, 1, 1); CP_COMMIT();

    const uint32_t aQh = sb + (uint32_t)(((lane & 15) * 136 + (lane >> 4) * 8)) * 2;
    const uint32_t aQl = aQh + 4352;
    const uint32_t boffK = (uint32_t)(((lane & 7) * 136 + (lane >> 3) * 8)) * 2;

    const int gr = lane >> 2;
    const int tq = lane & 3;

    // ---- Phase 1: S = Q K^T (registers), pipelined K chunks ----
    float s[8][4];
#pragma unroll
    for (int ti = 0; ti < 8; ti++)
#pragma unroll
        for (int j = 0; j < 4; j++) s[ti][j] = 0.f;

    for (int ch = 0; ch < 4; ch++) {
        CP_WAIT1();
        __syncthreads();
        const int st = ch & 1;
        const uint32_t bKh = sb + (uint32_t)(4352 + st * 17408) * 2 + boffK;
        const uint32_t bKl = bKh + 17408;

#pragma unroll
        for (int kp = 0; kp < 4; kp++) {
            uint32_t ah0[4], ah1[4], al0[4], al1[4];
            ldsm_x4(aQh + kp * 64,      ah0);
            ldsm_x4(aQh + kp * 64 + 32, ah1);
            ldsm_x4(aQl + kp * 64,      al0);
            ldsm_x4(aQl + kp * 64 + 32, al1);
#pragma unroll
            for (int nt = 0; nt < 2; nt++) {
                int ti = ch * 2 + nt;
                uint32_t bofs = (uint32_t)(((wn * 16 + nt * 8) * 136) * 2) + kp * 64;
                uint32_t bh[4], bl[4];
                ldsm_x4(bKh + bofs, bh);
                ldsm_x4(bKl + bofs, bl);
                mma_bf16(s[ti], ah0, bh);
                mma_bf16(s[ti], ah0, bl);
                mma_bf16(s[ti], al0, bh);
                mma_bf16(s[ti], ah1, bh + 2);
                mma_bf16(s[ti], ah1, bl + 2);
                mma_bf16(s[ti], al1, bh + 2);
            }
        }
        __syncthreads();
        if (ch < 2) cpKV(g_kh, g_kl, ch + 2, st);
        else        cpKV(g_vh, g_vl, ch - 2, st);
        CP_COMMIT();
    }

    // ---- bias (smem) + row max ----
    float mx0 = -1e30f, mx1 = -1e30f;
#pragma unroll
    for (int ti = 0; ti < 8; ti++) {
        int col = (ti >> 1) * 64 + wn * 16 + (ti & 1) * 8 + tq * 2;
        float2 b0 = *(const float2*)(sBiasF + gr * 260 + col);
        float2 b1 = *(const float2*)(sBiasF + (gr + 8) * 260 + col);
        s[ti][0] = s[ti][0] * RSCALE + b0.x;
        s[ti][1] = s[ti][1] * RSCALE + b0.y;
        s[ti][2] = s[ti][2] * RSCALE + b1.x;
        s[ti][3] = s[ti][3] * RSCALE + b1.y;
        mx0 = fmaxf(mx0, fmaxf(s[ti][0], s[ti][1]));
        mx1 = fmaxf(mx1, fmaxf(s[ti][2], s[ti][3]));
    }
    mx0 = fmaxf(mx0, __shfl_xor_sync(0xffffffffu, mx0, 1));
    mx0 = fmaxf(mx0, __shfl_xor_sync(0xffffffffu, mx0, 2));
    mx1 = fmaxf(mx1, __shfl_xor_sync(0xffffffffu, mx1, 1));
    mx1 = fmaxf(mx1, __shfl_xor_sync(0xffffffffu, mx1, 2));
    if (tq == 0) {
        sMax[gr * 4 + wn]       = mx0;
        sMax[(gr + 8) * 4 + wn] = mx1;
    }
    __syncthreads();
    mx0 = fmaxf(fmaxf(sMax[gr * 4 + 0], sMax[gr * 4 + 1]),
                fmaxf(sMax[gr * 4 + 2], sMax[gr * 4 + 3]));
    mx1 = fmaxf(fmaxf(sMax[(gr + 8) * 4 + 0], sMax[(gr + 8) * 4 + 1]),
                fmaxf(sMax[(gr + 8) * 4 + 2], sMax[(gr + 8) * 4 + 3]));

    // ---- exp + sum; P -> smem split-bf16 ----
    float sum0 = 0.f, sum1 = 0.f;
#pragma unroll
    for (int ti = 0; ti < 8; ti++) {
        int col = (ti >> 1) * 64 + wn * 16 + (ti & 1) * 8 + tq * 2;
        float e0 = __expf(s[ti][0] - mx0);
        float e1 = __expf(s[ti][1] - mx0);
        float e2 = __expf(s[ti][2] - mx1);
        float e3 = __expf(s[ti][3] - mx1);
        sum0 += e0 + e1;
        sum1 += e2 + e3;
        uint32_t lo0, lo1;
        uint32_t hi0 = split_pack(e0, e1, &lo0);
        uint32_t hi1 = split_pack(e2, e3, &lo1);
        *(uint32_t*)(sPh + gr * 264 + col)       = hi0;
        *(uint32_t*)(sPl + gr * 264 + col)       = lo0;
        *(uint32_t*)(sPh + (gr + 8) * 264 + col) = hi1;
        *(uint32_t*)(sPl + (gr + 8) * 264 + col) = lo1;
    }
    sum0 += __shfl_xor_sync(0xffffffffu, sum0, 1);
    sum0 += __shfl_xor_sync(0xffffffffu, sum0, 2);
    sum1 += __shfl_xor_sync(0xffffffffu, sum1, 1);
    sum1 += __shfl_xor_sync(0xffffffffu, sum1, 2);
    if (tq == 0) {
        sSum[gr * 4 + wn]       = sum0;
        sSum[(gr + 8) * 4 + wn] = sum1;
    }

    // ---- Phase 2: O = P V, pipelined V chunks ----
    float o[4][4];
#pragma unroll
    for (int nt = 0; nt < 4; nt++)
#pragma unroll
        for (int j = 0; j < 4; j++) o[nt][j] = 0.f;

    const uint32_t aPh = sb + (uint32_t)(39168 * 2) +
        (uint32_t)(((lane & 15) * 264 + (lane >> 4) * 8)) * 2;
    const uint32_t aPl = aPh + 8448;
    const uint32_t boffV =
        (uint32_t)((((lane & 7) + (lane & 8)) * 136 + ((lane >> 4) & 1) * 8)) * 2;

    for (int ch = 0; ch < 4; ch++) {
        if (ch == 3) { CP_WAIT0(); } else { CP_WAIT1(); }
        __syncthreads();
        const int st = ch & 1;
        const uint32_t bVh = sb + (uint32_t)(4352 + st * 17408) * 2 + boffV;
        const uint32_t bVl = bVh + 17408;

#pragma unroll
        for (int kt = 0; kt < 4; kt++) {
            uint32_t ph[4], pl[4];
            ldsm_x4(aPh + (ch * 64 + kt * 16) * 2, ph);
            ldsm_x4(aPl + (ch * 64 + kt * 16) * 2, pl);
#pragma unroll
            for (int np = 0; np < 2; np++) {
                uint32_t vofs = (uint32_t)((kt * 16 * 136 + wn * 32 + np * 16) * 2);
                uint32_t vh[4], vl[4];
                ldsm_x4_t(bVh + vofs, vh);
                ldsm_x4_t(bVl + vofs, vl);
                mma_bf16(o[np * 2],     ph, vh);
                mma_bf16(o[np * 2],     ph, vl);
                mma_bf16(o[np * 2],     pl, vh);
                mma_bf16(o[np * 2 + 1], ph, vh + 2);
                mma_bf16(o[np * 2 + 1], ph, vl + 2);
                mma_bf16(o[np * 2 + 1], pl, vh + 2);
            }
        }
        __syncthreads();
        if (ch < 2) { cpKV(g_vh, g_vl, ch + 2, st); CP_COMMIT(); }
    }

    // ---- epilogue: normalize, store ----
    float r0inv = 1.0f / (sSum[gr * 4 + 0] + sSum[gr * 4 + 1] +
                          sSum[gr * 4 + 2] + sSum[gr * 4 + 3]);
    float r1inv = 1.0f / (sSum[(gr + 8) * 4 + 0] + sSum[(gr + 8) * 4 + 1] +
                          sSum[(gr + 8) * 4 + 2] + sSum[(gr + 8) * 4 + 3]);
    int row0 = nbase + gr;
#pragma unroll
    for (int nt = 0; nt < 4; nt++) {
        int col = wn * 32 + nt * 8 + tq * 2;
        *(float2*)(out + row0 * DD + col) =
            make_float2(o[nt][0] * r0inv, o[nt][1] * r0inv);
        *(float2*)(out + (row0 + 8) * DD + col) =
            make_float2(o[nt][2] * r1inv, o[nt][3] * r1inv);
    }
}

// =====================================================================
extern "C" void kernel_launch(void* const* d_in, const int* in_sizes, int n_in,
                              void* d_out, int out_size)
{
    const float* x    = (const float*)d_in[0];
    const float* bmat = (const float*)d_in[1];
    const float* cmat = (const float*)d_in[2];
    // d_in[3] = ptr (uniform graph layout: NPG = 256; unused)
    const int*   mask = (const int*)d_in[4];
    const float* Wq   = (const float*)d_in[5];
    const float* bq   = (const float*)d_in[6];
    const float* Wk   = (const float*)d_in[7];
    const float* bk   = (const float*)d_in[8];
    const float* Wv   = (const float*)d_in[9];
    const float* bv   = (const float*)d_in[10];
    float* out = (float*)d_out;

    cudaFuncSetAttribute(qkv_mma_kernel, cudaFuncAttributeMaxDynamicSharedMemorySize,
                         QKV_SMEM_BYTES);
    cudaFuncSetAttribute(attn_mma_kernel, cudaFuncAttributeMaxDynamicSharedMemorySize,
                         ATTN_SMEM);

    prep_bias_kernel<<<(NN * NPG / 4) / 256, 256>>>(bmat, cmat, mask);
    convert_x_kernel<<<(NN * DIN / 4) / 256, 256>>>(x);
    convert_w_kernel<<<(3 * DD * DIN / 4) / 256, 256>>>(Wq, Wk, Wv);
    qkv_mma_kernel<<<dim3(128, 3), 128, QKV_SMEM_BYTES>>>(bq, bk, bv);
    attn_mma_kernel<<<dim3(16, 16), 128, ATTN_SMEM>>>(out);
}

// round 14
// speedup vs baseline: 1.0240x; 1.0005x over previous
#include <cuda_runtime.h>
#include <cuda_bf16.h>
#include <cstdint>
#include <math.h>

#define NN    4096
#define DIN   512
#define DD    128
#define NG    16
#define NPG   256
#define RSCALE 0.08838834764831843f   // 1/sqrt(128)

// ---------------- device scratch (allocation-free) ----------------
__device__ __nv_bfloat16 g_qh[NN * DD];
__device__ __nv_bfloat16 g_ql[NN * DD];
__device__ __nv_bfloat16 g_kh[NN * DD];
__device__ __nv_bfloat16 g_kl[NN * DD];
__device__ __nv_bfloat16 g_vh[NN * DD];
__device__ __nv_bfloat16 g_vl[NN * DD];
__device__ __nv_bfloat16 g_xh[NN * DIN];
__device__ __nv_bfloat16 g_xl[NN * DIN];
__device__ __nv_bfloat16 g_wh[3 * DD * DIN];
__device__ __nv_bfloat16 g_wl[3 * DD * DIN];
__device__ float g_bias[NN * NPG];   // compact block-diagonal masked bias

// ---------------- helpers ----------------
static __device__ __forceinline__ uint32_t smem_u32(const void* p) {
    uint32_t a;
    asm("{ .reg .u64 t; cvta.to.shared.u64 t, %1; cvt.u32.u64 %0, t; }" : "=r"(a) : "l"(p));
    return a;
}
static __device__ __forceinline__ void ldsm_x4(uint32_t addr, uint32_t* r) {
    asm volatile("ldmatrix.sync.aligned.m8n8.x4.shared.b16 {%0,%1,%2,%3}, [%4];"
                 : "=r"(r[0]), "=r"(r[1]), "=r"(r[2]), "=r"(r[3]) : "r"(addr));
}
static __device__ __forceinline__ void ldsm_x4_t(uint32_t addr, uint32_t* r) {
    asm volatile("ldmatrix.sync.aligned.m8n8.x4.trans.shared.b16 {%0,%1,%2,%3}, [%4];"
                 : "=r"(r[0]), "=r"(r[1]), "=r"(r[2]), "=r"(r[3]) : "r"(addr));
}
static __device__ __forceinline__ void mma_bf16(float* c, const uint32_t* a, const uint32_t* b) {
    asm volatile(
        "mma.sync.aligned.m16n8k16.row.col.f32.bf16.bf16.f32 "
        "{%0,%1,%2,%3}, {%4,%5,%6,%7}, {%8,%9}, {%0,%1,%2,%3};"
        : "+f"(c[0]), "+f"(c[1]), "+f"(c[2]), "+f"(c[3])
        : "r"(a[0]), "r"(a[1]), "r"(a[2]), "r"(a[3]), "r"(b[0]), "r"(b[1]));
}
static __device__ __forceinline__ uint32_t split_pack(float a, float b, uint32_t* lo) {
    __nv_bfloat16 ha = __float2bfloat16(a), hb = __float2bfloat16(b);
    __nv_bfloat16 la = __float2bfloat16(a - __bfloat162float(ha));
    __nv_bfloat16 lb = __float2bfloat16(b - __bfloat162float(hb));
    *lo = (uint32_t)__bfloat16_as_ushort(la) | ((uint32_t)__bfloat16_as_ushort(lb) << 16);
    return (uint32_t)__bfloat16_as_ushort(ha) | ((uint32_t)__bfloat16_as_ushort(hb) << 16);
}
#define CPA16(dst, src) \
    asm volatile("cp.async.cg.shared.global [%0], [%1], 16;" :: "r"(dst), "l"(src))
#define CP_COMMIT() asm volatile("cp.async.commit_group;" ::: "memory")
#define CP_WAIT0()  asm volatile("cp.async.wait_group 0;" ::: "memory")
#define CP_WAIT1()  asm volatile("cp.async.wait_group 1;" ::: "memory")

// =====================================================================
// Kernel P: compact masked bias  g_bias[n][j] = keep ? b+c : -1e30
// =====================================================================
__global__ void __launch_bounds__(256) prep_bias_kernel(
    const float* __restrict__ b, const float* __restrict__ c, const int* __restrict__ mask)
{
    int i = blockIdx.x * 256 + threadIdx.x;
    int e = i * 4;
    int row = e >> 8;
    int col = e & 255;
    int kb  = (row >> 8) << 8;
    size_t idx = (size_t)row * NN + kb + col;
    float4 bv = *(const float4*)(b + idx);
    float4 cv = *(const float4*)(c + idx);
    int4   mv = *(const int4*)(mask + idx);
    float4 o;
    o.x = mv.x ? bv.x + cv.x : -1e30f;
    o.y = mv.y ? bv.y + cv.y : -1e30f;
    o.z = mv.z ? bv.z + cv.z : -1e30f;
    o.w = mv.w ? bv.w + cv.w : -1e30f;
    *(float4*)(g_bias + e) = o;
}

// =====================================================================
// Kernel 0a/0b: split converts
// =====================================================================
__global__ void __launch_bounds__(256) convert_x_kernel(const float* __restrict__ x)
{
    int i = blockIdx.x * 256 + threadIdx.x;
    float4 v = ((const float4*)x)[i];
    uint2 hp, lp;
    hp.x = split_pack(v.x, v.y, &lp.x);
    hp.y = split_pack(v.z, v.w, &lp.y);
    ((uint2*)g_xh)[i] = hp;
    ((uint2*)g_xl)[i] = lp;
}
__global__ void __launch_bounds__(256) convert_w_kernel(
    const float* __restrict__ Wq, const float* __restrict__ Wk, const float* __restrict__ Wv)
{
    int i = blockIdx.x * 256 + threadIdx.x;
    int fidx = i * 4;
    int row = fidx >> 9;
    int col = fidx & 511;
    const float* src = (row < 128) ? (Wq + row * 512)
                     : (row < 256) ? (Wk + (row - 128) * 512)
                                   : (Wv + (row - 256) * 512);
    float4 v = *(const float4*)(src + col);
    uint2 hp, lp;
    hp.x = split_pack(v.x, v.y, &lp.x);
    hp.y = split_pack(v.z, v.w, &lp.y);
    ((uint2*)g_wh)[i] = hp;
    ((uint2*)g_wl)[i] = lp;
}

// =====================================================================
// Kernel 1: QKV projection, cp.async 2-stage pipelined mma.sync.
// grid (128, 3), block 128. Dynamic smem 90KB (2 stages).
// layout (bf16 elems): A: s*4608 + p*2304 ; B: 9216 + s*18432 + p*9216
// =====================================================================
#define QKV_SMEM_BYTES (46080 * 2)

__global__ void __launch_bounds__(128) qkv_mma_kernel(
    const float* __restrict__ bq, const float* __restrict__ bk, const float* __restrict__ bv)
{
    extern __shared__ __nv_bfloat16 dsm[];
    const uint32_t sb = smem_u32(dsm);

    const int t    = threadIdx.x;
    const int lane = t & 31;
    const int wid  = t >> 5;
    const int m0   = blockIdx.x * 32;
    const int z    = blockIdx.y;

    const __nv_bfloat16* Wh = g_wh + z * DD * DIN;
    const __nv_bfloat16* Wl = g_wl + z * DD * DIN;
    const float* bias = (z == 0) ? bq : ((z == 1) ? bk : bv);
    __nv_bfloat16* outh = (z == 0) ? g_qh : ((z == 1) ? g_kh : g_vh);
    __nv_bfloat16* outl = (z == 0) ? g_ql : ((z == 1) ? g_kl : g_vl);

    const int wm = wid & 1;
    const int wn = wid >> 1;

    auto preload = [&](int ch, int s) {
        uint32_t aBase = sb + (uint32_t)(s * 4608) * 2;
        uint32_t bBase = sb + (uint32_t)(9216 + s * 18432) * 2;
#pragma unroll
        for (int j = 0; j < 2; j++) {
            int c = t + j * 128, row = c >> 3, o8 = (c & 7) * 8;
            uint32_t d = aBase + (uint32_t)(row * 72 + o8) * 2;
            const int gsrc = (m0 + row) * DIN + ch * 64 + o8;
            CPA16(d,        g_xh + gsrc);
            CPA16(d + 4608, g_xl + gsrc);
        }
#pragma unroll
        for (int j = 0; j < 8; j++) {
            int c = t + j * 128, row = c >> 3, o8 = (c & 7) * 8;
            uint32_t d = bBase + (uint32_t)(row * 72 + o8) * 2;
            const int gsrc = row * DIN + ch * 64 + o8;
            CPA16(d,         Wh + gsrc);
            CPA16(d + 18432, Wl + gsrc);
        }
    };

    float acc[8][4];
#pragma unroll
    for (int nt = 0; nt < 8; nt++)
#pragma unroll
        for (int j = 0; j < 4; j++) acc[nt][j] = 0.f;

    const uint32_t aoff = (uint32_t)(((wm * 16 + (lane & 15)) * 72 + ((lane >> 4) * 8)) * 2);
    const uint32_t boff = (uint32_t)((((lane & 7)) * 72 + ((lane >> 3) * 8)) * 2);

    preload(0, 0); CP_COMMIT();
    preload(1, 1); CP_COMMIT();

    for (int ch = 0; ch < 8; ch++) {
        if (ch == 7) { CP_WAIT0(); } else { CP_WAIT1(); }
        __syncthreads();

        const int s = ch & 1;
        const uint32_t aAh = sb + (uint32_t)(s * 4608) * 2 + aoff;
        const uint32_t aAl = aAh + 4608;
        const uint32_t aBh = sb + (uint32_t)(9216 + s * 18432) * 2 + boff;
        const uint32_t aBl = aBh + 18432;

        uint32_t ah[4][4], al[4][4];
#pragma unroll
        for (int ks = 0; ks < 4; ks++) {
            ldsm_x4(aAh + ks * 32, ah[ks]);
            ldsm_x4(aAl + ks * 32, al[ks]);
        }
#pragma unroll
        for (int nt = 0; nt < 8; nt++) {
            uint32_t bofs = (uint32_t)((wn * 64 + nt * 8) * 144);
#pragma unroll
            for (int kp = 0; kp < 2; kp++) {
                uint32_t bh[4], bl[4];
                ldsm_x4(aBh + bofs + kp * 64, bh);
                ldsm_x4(aBl + bofs + kp * 64, bl);
                mma_bf16(acc[nt], ah[kp * 2],     bh);
                mma_bf16(acc[nt], ah[kp * 2],     bl);
                mma_bf16(acc[nt], al[kp * 2],     bh);
                mma_bf16(acc[nt], ah[kp * 2 + 1], bh + 2);
                mma_bf16(acc[nt], ah[kp * 2 + 1], bl + 2);
                mma_bf16(acc[nt], al[kp * 2 + 1], bh + 2);
            }
        }
        __syncthreads();
        if (ch + 2 < 8) { preload(ch + 2, s); CP_COMMIT(); }
    }

    const int gr = lane >> 2;
    const int tq = lane & 3;
    const int row = m0 + wm * 16 + gr;
#pragma unroll
    for (int nt = 0; nt < 8; nt++) {
        int col = wn * 64 + nt * 8 + tq * 2;
        float2 bz = *(const float2*)(bias + col);
        uint32_t lo0, lo1;
        uint32_t hi0 = split_pack(acc[nt][0] + bz.x, acc[nt][1] + bz.y, &lo0);
        uint32_t hi1 = split_pack(acc[nt][2] + bz.x, acc[nt][3] + bz.y, &lo1);
        *(uint32_t*)(outh + row * DD + col)       = hi0;
        *(uint32_t*)(outl + row * DD + col)       = lo0;
        *(uint32_t*)(outh + (row + 8) * DD + col) = hi1;
        *(uint32_t*)(outl + (row + 8) * DD + col) = lo1;
    }
}

// =====================================================================
// Kernel 2: block-diagonal attention, cp.async 2-stage pipelined.
// grid (16, 16), block 128 (4 warps col-split). Dynamic smem ~110KB.
// bf16-elem layout:
//   Q  hi 0 / lo 2176                              (total 4352)
//   KV base 4352, stage stride 17408, part 8704    (total 34816)
//   P  base 39168 hi / 43392 lo                    (total 8448) -> end 47616
// byte layout after bf16 region (95232B):
//   bias float[16][260] @95232 ; sMax @111872 ; sSum @112128 ; total 112384
// =====================================================================
#define ATTN_SMEM 112384

__global__ void __launch_bounds__(128) attn_mma_kernel(float* __restrict__ out)
{
    extern __shared__ __nv_bfloat16 dsm[];
    const uint32_t sb = smem_u32(dsm);
    __nv_bfloat16* sPh = dsm + 39168;
    __nv_bfloat16* sPl = dsm + 43392;
    float* sBiasF = (float*)((char*)dsm + 95232);
    float* sMax   = (float*)((char*)dsm + 111872);
    float* sSum   = sMax + 64;

    const int t    = threadIdx.x;
    const int lane = t & 31;
    const int wn   = t >> 5;
    const int g    = blockIdx.y;
    const int nbase = g * NPG + blockIdx.x * 16;
    const int kbase = g * NPG;

    auto cpKV = [&](const __nv_bfloat16* srcH, const __nv_bfloat16* srcL, int ch, int s) {
        uint32_t base = sb + (uint32_t)(4352 + s * 17408) * 2;
        int row = t >> 1, c0 = (t & 1) * 64;
        const int gsrc = (kbase + ch * 64 + row) * DD + c0;
#pragma unroll
        for (int i = 0; i < 8; i++) {
            uint32_t d = base + (uint32_t)(row * 136 + c0 + i * 8) * 2;
            CPA16(d,         srcH + gsrc + i * 8);
            CPA16(d + 17408, srcL + gsrc + i * 8);
        }
    };

    // ---- group 1: Q + bias + K0 ; group 2: K1 ----
    {
        int row = t >> 3, c0 = (t & 7) * 16;
        const int gsrc = (nbase + row) * DD + c0;
#pragma unroll
        for (int i = 0; i < 2; i++) {
            uint32_t d = sb + (uint32_t)(row * 136 + c0 + i * 8) * 2;
            CPA16(d,        g_qh + gsrc + i * 8);
            CPA16(d + 4352, g_ql + gsrc + i * 8);
        }
        int bcol = (t & 7) * 32;
        const float* bsrc = g_bias + (nbase + row) * NPG + bcol;
        uint32_t bdst = sb + 95232 + (uint32_t)(row * 260 + bcol) * 4;
#pragma unroll
        for (int i = 0; i < 8; i++)
            CPA16(bdst + i * 16, bsrc + i * 4);
    }
    cpKV(g_kh, g_kl, 0, 0); CP_COMMIT();
    cpKV(g_kh, g_kl, 1, 1); CP_COMMIT();

    const uint32_t aQh = sb + (uint32_t)(((lane & 15) * 136 + (lane >> 4) * 8)) * 2;
    const uint32_t aQl = aQh + 4352;
    const uint32_t boffK = (uint32_t)(((lane & 7) * 136 + (lane >> 3) * 8)) * 2;

    const int gr = lane >> 2;
    const int tq = lane & 3;

    // ---- Phase 1: S = Q K^T (registers), pipelined K chunks ----
    float s[8][4];
#pragma unroll
    for (int ti = 0; ti < 8; ti++)
#pragma unroll
        for (int j = 0; j < 4; j++) s[ti][j] = 0.f;

    for (int ch = 0; ch < 4; ch++) {
        CP_WAIT1();
        __syncthreads();
        const int st = ch & 1;
        const uint32_t bKh = sb + (uint32_t)(4352 + st * 17408) * 2 + boffK;
        const uint32_t bKl = bKh + 17408;

#pragma unroll
        for (int kp = 0; kp < 4; kp++) {
            uint32_t ah0[4], ah1[4], al0[4], al1[4];
            ldsm_x4(aQh + kp * 64,      ah0);
            ldsm_x4(aQh + kp * 64 + 32, ah1);
            ldsm_x4(aQl + kp * 64,      al0);
            ldsm_x4(aQl + kp * 64 + 32, al1);
#pragma unroll
            for (int nt = 0; nt < 2; nt++) {
                int ti = ch * 2 + nt;
                uint32_t bofs = (uint32_t)(((wn * 16 + nt * 8) * 136) * 2) + kp * 64;
                uint32_t bh[4], bl[4];
                ldsm_x4(bKh + bofs, bh);
                ldsm_x4(bKl + bofs, bl);
                mma_bf16(s[ti], ah0, bh);
                mma_bf16(s[ti], ah0, bl);
                mma_bf16(s[ti], al0, bh);
                mma_bf16(s[ti], ah1, bh + 2);
                mma_bf16(s[ti], ah1, bl + 2);
                mma_bf16(s[ti], al1, bh + 2);
            }
        }
        __syncthreads();
        if (ch < 2) cpKV(g_kh, g_kl, ch + 2, st);
        else        cpKV(g_vh, g_vl, ch - 2, st);
        CP_COMMIT();
    }

    // ---- bias (smem) + row max ----
    float mx0 = -1e30f, mx1 = -1e30f;
#pragma unroll
    for (int ti = 0; ti < 8; ti++) {
        int col = (ti >> 1) * 64 + wn * 16 + (ti & 1) * 8 + tq * 2;
        float2 b0 = *(const float2*)(sBiasF + gr * 260 + col);
        float2 b1 = *(const float2*)(sBiasF + (gr + 8) * 260 + col);
        s[ti][0] = s[ti][0] * RSCALE + b0.x;
        s[ti][1] = s[ti][1] * RSCALE + b0.y;
        s[ti][2] = s[ti][2] * RSCALE + b1.x;
        s[ti][3] = s[ti][3] * RSCALE + b1.y;
        mx0 = fmaxf(mx0, fmaxf(s[ti][0], s[ti][1]));
        mx1 = fmaxf(mx1, fmaxf(s[ti][2], s[ti][3]));
    }
    mx0 = fmaxf(mx0, __shfl_xor_sync(0xffffffffu, mx0, 1));
    mx0 = fmaxf(mx0, __shfl_xor_sync(0xffffffffu, mx0, 2));
    mx1 = fmaxf(mx1, __shfl_xor_sync(0xffffffffu, mx1, 1));
    mx1 = fmaxf(mx1, __shfl_xor_sync(0xffffffffu, mx1, 2));
    if (tq == 0) {
        sMax[gr * 4 + wn]       = mx0;
        sMax[(gr + 8) * 4 + wn] = mx1;
    }
    __syncthreads();
    mx0 = fmaxf(fmaxf(sMax[gr * 4 + 0], sMax[gr * 4 + 1]),
                fmaxf(sMax[gr * 4 + 2], sMax[gr * 4 + 3]));
    mx1 = fmaxf(fmaxf(sMax[(gr + 8) * 4 + 0], sMax[(gr + 8) * 4 + 1]),
                fmaxf(sMax[(gr + 8) * 4 + 2], sMax[(gr + 8) * 4 + 3]));

    // ---- exp + sum; P -> smem split-bf16 ----
    float sum0 = 0.f, sum1 = 0.f;
#pragma unroll
    for (int ti = 0; ti < 8; ti++) {
        int col = (ti >> 1) * 64 + wn * 16 + (ti & 1) * 8 + tq * 2;
        float e0 = __expf(s[ti][0] - mx0);
        float e1 = __expf(s[ti][1] - mx0);
        float e2 = __expf(s[ti][2] - mx1);
        float e3 = __expf(s[ti][3] - mx1);
        sum0 += e0 + e1;
        sum1 += e2 + e3;
        uint32_t lo0, lo1;
        uint32_t hi0 = split_pack(e0, e1, &lo0);
        uint32_t hi1 = split_pack(e2, e3, &lo1);
        *(uint32_t*)(sPh + gr * 264 + col)       = hi0;
        *(uint32_t*)(sPl + gr * 264 + col)       = lo0;
        *(uint32_t*)(sPh + (gr + 8) * 264 + col) = hi1;
        *(uint32_t*)(sPl + (gr + 8) * 264 + col) = lo1;
    }
    sum0 += __shfl_xor_sync(0xffffffffu, sum0, 1);
    sum0 += __shfl_xor_sync(0xffffffffu, sum0, 2);
    sum1 += __shfl_xor_sync(0xffffffffu, sum1, 1);
    sum1 += __shfl_xor_sync(0xffffffffu, sum1, 2);
    if (tq == 0) {
        sSum[gr * 4 + wn]       = sum0;
        sSum[(gr + 8) * 4 + wn] = sum1;
    }

    // ---- Phase 2: O = P V, pipelined V chunks ----
    float o[4][4];
#pragma unroll
    for (int nt = 0; nt < 4; nt++)
#pragma unroll
        for (int j = 0; j < 4; j++) o[nt][j] = 0.f;

    const uint32_t aPh = sb + (uint32_t)(39168 * 2) +
        (uint32_t)(((lane & 15) * 264 + (lane >> 4) * 8)) * 2;
    const uint32_t aPl = aPh + 8448;
    const uint32_t boffV =
        (uint32_t)((((lane & 7) + (lane & 8)) * 136 + ((lane >> 4) & 1) * 8)) * 2;

    for (int ch = 0; ch < 4; ch++) {
        if (ch == 3) { CP_WAIT0(); } else { CP_WAIT1(); }
        __syncthreads();
        const int st = ch & 1;
        const uint32_t bVh = sb + (uint32_t)(4352 + st * 17408) * 2 + boffV;
        const uint32_t bVl = bVh + 17408;

#pragma unroll
        for (int kt = 0; kt < 4; kt++) {
            uint32_t ph[4], pl[4];
            ldsm_x4(aPh + (ch * 64 + kt * 16) * 2, ph);
            ldsm_x4(aPl + (ch * 64 + kt * 16) * 2, pl);
#pragma unroll
            for (int np = 0; np < 2; np++) {
                uint32_t vofs = (uint32_t)((kt * 16 * 136 + wn * 32 + np * 16) * 2);
                uint32_t vh[4], vl[4];
                ldsm_x4_t(bVh + vofs, vh);
                ldsm_x4_t(bVl + vofs, vl);
                mma_bf16(o[np * 2],     ph, vh);
                mma_bf16(o[np * 2],     ph, vl);
                mma_bf16(o[np * 2],     pl, vh);
                mma_bf16(o[np * 2 + 1], ph, vh + 2);
                mma_bf16(o[np * 2 + 1], ph, vl + 2);
                mma_bf16(o[np * 2 + 1], pl, vh + 2);
            }
        }
        __syncthreads();
        if (ch < 2) { cpKV(g_vh, g_vl, ch + 2, st); CP_COMMIT(); }
    }

    // ---- epilogue: normalize, store ----
    float r0inv = 1.0f / (sSum[gr * 4 + 0] + sSum[gr * 4 + 1] +
                          sSum[gr * 4 + 2] + sSum[gr * 4 + 3]);
    float r1inv = 1.0f / (sSum[(gr + 8) * 4 + 0] + sSum[(gr + 8) * 4 + 1] +
                          sSum[(gr + 8) * 4 + 2] + sSum[(gr + 8) * 4 + 3]);
    int row0 = nbase + gr;
#pragma unroll
    for (int nt = 0; nt < 4; nt++) {
        int col = wn * 32 + nt * 8 + tq * 2;
        *(float2*)(out + row0 * DD + col) =
            make_float2(o[nt][0] * r0inv, o[nt][1] * r0inv);
        *(float2*)(out + (row0 + 8) * DD + col) =
            make_float2(o[nt][2] * r1inv, o[nt][3] * r1inv);
    }
}

// =====================================================================
extern "C" void kernel_launch(void* const* d_in, const int* in_sizes, int n_in,
                              void* d_out, int out_size)
{
    const float* x    = (const float*)d_in[0];
    const float* bmat = (const float*)d_in[1];
    const float* cmat = (const float*)d_in[2];
    // d_in[3] = ptr (uniform graph layout: NPG = 256; unused)
    const int*   mask = (const int*)d_in[4];
    const float* Wq   = (const float*)d_in[5];
    const float* bq   = (const float*)d_in[6];
    const float* Wk   = (const float*)d_in[7];
    const float* bk   = (const float*)d_in[8];
    const float* Wv   = (const float*)d_in[9];
    const float* bv   = (const float*)d_in[10];
    float* out = (float*)d_out;

    cudaFuncSetAttribute(qkv_mma_kernel, cudaFuncAttributeMaxDynamicSharedMemorySize,
                         QKV_SMEM_BYTES);
    cudaFuncSetAttribute(attn_mma_kernel, cudaFuncAttributeMaxDynamicSharedMemorySize,
                         ATTN_SMEM);

    prep_bias_kernel<<<(NN * NPG / 4) / 256, 256>>>(bmat, cmat, mask);
    convert_x_kernel<<<(NN * DIN / 4) / 256, 256>>>(x);
    convert_w_kernel<<<(3 * DD * DIN / 4) / 256, 256>>>(Wq, Wk, Wv);
    qkv_mma_kernel<<<dim3(128, 3), 128, QKV_SMEM_BYTES>>>(bq, bk, bv);
    attn_mma_kernel<<<dim3(16, 16), 128, ATTN_SMEM>>>(out);
}

// round 16
// speedup vs baseline: 1.0250x; 1.0010x over previous
#include <cuda_runtime.h>
#include <cuda_bf16.h>
#include <cstdint>
#include <math.h>

#define NN    4096
#define DIN   512
#define DD    128
#define NG    16
#define NPG   256
#define RSCALE 0.08838834764831843f   // 1/sqrt(128)

// ---------------- device scratch (allocation-free) ----------------
__device__ __nv_bfloat16 g_qh[NN * DD];
__device__ __nv_bfloat16 g_ql[NN * DD];
__device__ __nv_bfloat16 g_kh[NN * DD];
__device__ __nv_bfloat16 g_kl[NN * DD];
__device__ __nv_bfloat16 g_vh[NN * DD];
__device__ __nv_bfloat16 g_vl[NN * DD];
__device__ __nv_bfloat16 g_xh[NN * DIN];
__device__ __nv_bfloat16 g_xl[NN * DIN];
__device__ __nv_bfloat16 g_wh[3 * DD * DIN];
__device__ __nv_bfloat16 g_wl[3 * DD * DIN];
__device__ float g_bias[NN * NPG];   // compact block-diagonal masked bias

// ---------------- helpers ----------------
static __device__ __forceinline__ uint32_t smem_u32(const void* p) {
    uint32_t a;
    asm("{ .reg .u64 t; cvta.to.shared.u64 t, %1; cvt.u32.u64 %0, t; }" : "=r"(a) : "l"(p));
    return a;
}
static __device__ __forceinline__ void ldsm_x4(uint32_t addr, uint32_t* r) {
    asm volatile("ldmatrix.sync.aligned.m8n8.x4.shared.b16 {%0,%1,%2,%3}, [%4];"
                 : "=r"(r[0]), "=r"(r[1]), "=r"(r[2]), "=r"(r[3]) : "r"(addr));
}
static __device__ __forceinline__ void ldsm_x4_t(uint32_t addr, uint32_t* r) {
    asm volatile("ldmatrix.sync.aligned.m8n8.x4.trans.shared.b16 {%0,%1,%2,%3}, [%4];"
                 : "=r"(r[0]), "=r"(r[1]), "=r"(r[2]), "=r"(r[3]) : "r"(addr));
}
static __device__ __forceinline__ void mma_bf16(float* c, const uint32_t* a, const uint32_t* b) {
    asm volatile(
        "mma.sync.aligned.m16n8k16.row.col.f32.bf16.bf16.f32 "
        "{%0,%1,%2,%3}, {%4,%5,%6,%7}, {%8,%9}, {%0,%1,%2,%3};"
        : "+f"(c[0]), "+f"(c[1]), "+f"(c[2]), "+f"(c[3])
        : "r"(a[0]), "r"(a[1]), "r"(a[2]), "r"(a[3]), "r"(b[0]), "r"(b[1]));
}
static __device__ __forceinline__ uint32_t split_pack(float a, float b, uint32_t* lo) {
    __nv_bfloat16 ha = __float2bfloat16(a), hb = __float2bfloat16(b);
    __nv_bfloat16 la = __float2bfloat16(a - __bfloat162float(ha));
    __nv_bfloat16 lb = __float2bfloat16(b - __bfloat162float(hb));
    *lo = (uint32_t)__bfloat16_as_ushort(la) | ((uint32_t)__bfloat16_as_ushort(lb) << 16);
    return (uint32_t)__bfloat16_as_ushort(ha) | ((uint32_t)__bfloat16_as_ushort(hb) << 16);
}
#define CPA16(dst, src) \
    asm volatile("cp.async.cg.shared.global [%0], [%1], 16;" :: "r"(dst), "l"(src))
#define CP_COMMIT() asm volatile("cp.async.commit_group;" ::: "memory")
#define CP_WAIT0()  asm volatile("cp.async.wait_group 0;" ::: "memory")
#define CP_WAIT1()  asm volatile("cp.async.wait_group 1;" ::: "memory")

// =====================================================================
// Kernel P: compact masked bias  g_bias[n][j] = keep ? b+c : -1e30
// =====================================================================
__global__ void __launch_bounds__(256) prep_bias_kernel(
    const float* __restrict__ b, const float* __restrict__ c, const int* __restrict__ mask)
{
    int i = blockIdx.x * 256 + threadIdx.x;
    int e = i * 4;
    int row = e >> 8;
    int col = e & 255;
    int kb  = (row >> 8) << 8;
    size_t idx = (size_t)row * NN + kb + col;
    float4 bv = *(const float4*)(b + idx);
    float4 cv = *(const float4*)(c + idx);
    int4   mv = *(const int4*)(mask + idx);
    float4 o;
    o.x = mv.x ? bv.x + cv.x : -1e30f;
    o.y = mv.y ? bv.y + cv.y : -1e30f;
    o.z = mv.z ? bv.z + cv.z : -1e30f;
    o.w = mv.w ? bv.w + cv.w : -1e30f;
    *(float4*)(g_bias + e) = o;
}

// =====================================================================
// Kernel 0a/0b: split converts
// =====================================================================
__global__ void __launch_bounds__(256) convert_x_kernel(const float* __restrict__ x)
{
    int i = blockIdx.x * 256 + threadIdx.x;
    float4 v = ((const float4*)x)[i];
    uint2 hp, lp;
    hp.x = split_pack(v.x, v.y, &lp.x);
    hp.y = split_pack(v.z, v.w, &lp.y);
    ((uint2*)g_xh)[i] = hp;
    ((uint2*)g_xl)[i] = lp;
}
__global__ void __launch_bounds__(256) convert_w_kernel(
    const float* __restrict__ Wq, const float* __restrict__ Wk, const float* __restrict__ Wv)
{
    int i = blockIdx.x * 256 + threadIdx.x;
    int fidx = i * 4;
    int row = fidx >> 9;
    int col = fidx & 511;
    const float* src = (row < 128) ? (Wq + row * 512)
                     : (row < 256) ? (Wk + (row - 128) * 512)
                                   : (Wv + (row - 256) * 512);
    float4 v = *(const float4*)(src + col);
    uint2 hp, lp;
    hp.x = split_pack(v.x, v.y, &lp.x);
    hp.y = split_pack(v.z, v.w, &lp.y);
    ((uint2*)g_wh)[i] = hp;
    ((uint2*)g_wl)[i] = lp;
}

// =====================================================================
// Kernel 1: QKV projection, cp.async 2-stage pipelined mma.sync.
// grid (128, 3), block 128. Dynamic smem 90KB (2 stages).
// layout (bf16 elems): A: s*4608 + p*2304 ; B: 9216 + s*18432 + p*9216
// =====================================================================
#define QKV_SMEM_BYTES (46080 * 2)

__global__ void __launch_bounds__(128) qkv_mma_kernel(
    const float* __restrict__ bq, const float* __restrict__ bk, const float* __restrict__ bv)
{
    extern __shared__ __nv_bfloat16 dsm[];
    const uint32_t sb = smem_u32(dsm);

    const int t    = threadIdx.x;
    const int lane = t & 31;
    const int wid  = t >> 5;
    const int m0   = blockIdx.x * 32;
    const int z    = blockIdx.y;

    const __nv_bfloat16* Wh = g_wh + z * DD * DIN;
    const __nv_bfloat16* Wl = g_wl + z * DD * DIN;
    const float* bias = (z == 0) ? bq : ((z == 1) ? bk : bv);
    __nv_bfloat16* outh = (z == 0) ? g_qh : ((z == 1) ? g_kh : g_vh);
    __nv_bfloat16* outl = (z == 0) ? g_ql : ((z == 1) ? g_kl : g_vl);

    const int wm = wid & 1;
    const int wn = wid >> 1;

    auto preload = [&](int ch, int s) {
        uint32_t aBase = sb + (uint32_t)(s * 4608) * 2;
        uint32_t bBase = sb + (uint32_t)(9216 + s * 18432) * 2;
#pragma unroll
        for (int j = 0; j < 2; j++) {
            int c = t + j * 128, row = c >> 3, o8 = (c & 7) * 8;
            uint32_t d = aBase + (uint32_t)(row * 72 + o8) * 2;
            const int gsrc = (m0 + row) * DIN + ch * 64 + o8;
            CPA16(d,        g_xh + gsrc);
            CPA16(d + 4608, g_xl + gsrc);
        }
#pragma unroll
        for (int j = 0; j < 8; j++) {
            int c = t + j * 128, row = c >> 3, o8 = (c & 7) * 8;
            uint32_t d = bBase + (uint32_t)(row * 72 + o8) * 2;
            const int gsrc = row * DIN + ch * 64 + o8;
            CPA16(d,         Wh + gsrc);
            CPA16(d + 18432, Wl + gsrc);
        }
    };

    float acc[8][4];
#pragma unroll
    for (int nt = 0; nt < 8; nt++)
#pragma unroll
        for (int j = 0; j < 4; j++) acc[nt][j] = 0.f;

    const uint32_t aoff = (uint32_t)(((wm * 16 + (lane & 15)) * 72 + ((lane >> 4) * 8)) * 2);
    const uint32_t boff = (uint32_t)((((lane & 7)) * 72 + ((lane >> 3) * 8)) * 2);

    preload(0, 0); CP_COMMIT();
    preload(1, 1); CP_COMMIT();

    for (int ch = 0; ch < 8; ch++) {
        if (ch == 7) { CP_WAIT0(); } else { CP_WAIT1(); }
        __syncthreads();

        const int s = ch & 1;
        const uint32_t aAh = sb + (uint32_t)(s * 4608) * 2 + aoff;
        const uint32_t aAl = aAh + 4608;
        const uint32_t aBh = sb + (uint32_t)(9216 + s * 18432) * 2 + boff;
        const uint32_t aBl = aBh + 18432;

        uint32_t ah[4][4], al[4][4];
#pragma unroll
        for (int ks = 0; ks < 4; ks++) {
            ldsm_x4(aAh + ks * 32, ah[ks]);
            ldsm_x4(aAl + ks * 32, al[ks]);
        }
#pragma unroll
        for (int nt = 0; nt < 8; nt++) {
            uint32_t bofs = (uint32_t)((wn * 64 + nt * 8) * 144);
#pragma unroll
            for (int kp = 0; kp < 2; kp++) {
                uint32_t bh[4], bl[4];
                ldsm_x4(aBh + bofs + kp * 64, bh);
                ldsm_x4(aBl + bofs + kp * 64, bl);
                mma_bf16(acc[nt], ah[kp * 2],     bh);
                mma_bf16(acc[nt], ah[kp * 2],     bl);
                mma_bf16(acc[nt], al[kp * 2],     bh);
                mma_bf16(acc[nt], ah[kp * 2 + 1], bh + 2);
                mma_bf16(acc[nt], ah[kp * 2 + 1], bl + 2);
                mma_bf16(acc[nt], al[kp * 2 + 1], bh + 2);
            }
        }
        __syncthreads();
        if (ch + 2 < 8) { preload(ch + 2, s); CP_COMMIT(); }
    }

    const int gr = lane >> 2;
    const int tq = lane & 3;
    const int row = m0 + wm * 16 + gr;
#pragma unroll
    for (int nt = 0; nt < 8; nt++) {
        int col = wn * 64 + nt * 8 + tq * 2;
        float2 bz = *(const float2*)(bias + col);
        uint32_t lo0, lo1;
        uint32_t hi0 = split_pack(acc[nt][0] + bz.x, acc[nt][1] + bz.y, &lo0);
        uint32_t hi1 = split_pack(acc[nt][2] + bz.x, acc[nt][3] + bz.y, &lo1);
        *(uint32_t*)(outh + row * DD + col)       = hi0;
        *(uint32_t*)(outl + row * DD + col)       = lo0;
        *(uint32_t*)(outh + (row + 8) * DD + col) = hi1;
        *(uint32_t*)(outl + (row + 8) * DD + col) = lo1;
    }
}

// =====================================================================
// Kernel 2: block-diagonal attention, cp.async 2-stage pipelined.
// grid (16, 16), block 128 (4 warps col-split). Dynamic smem ~110KB.
// bf16-elem layout:
//   Q  hi 0 / lo 2176                              (total 4352)
//   KV base 4352, stage stride 17408, part 8704    (total 34816)
//   P  base 39168 hi / 43392 lo                    (total 8448) -> end 47616
// byte layout after bf16 region (95232B):
//   bias float[16][260] @95232 ; sMax @111872 ; sSum @112128 ; total 112384
// =====================================================================
#define ATTN_SMEM 112384

__global__ void __launch_bounds__(128) attn_mma_kernel(float* __restrict__ out)
{
    extern __shared__ __nv_bfloat16 dsm[];
    const uint32_t sb = smem_u32(dsm);
    __nv_bfloat16* sPh = dsm + 39168;
    __nv_bfloat16* sPl = dsm + 43392;
    float* sBiasF = (float*)((char*)dsm + 95232);
    float* sMax   = (float*)((char*)dsm + 111872);
    float* sSum   = sMax + 64;

    const int t    = threadIdx.x;
    const int lane = t & 31;
    const int wn   = t >> 5;
    const int g    = blockIdx.y;
    const int nbase = g * NPG + blockIdx.x * 16;
    const int kbase = g * NPG;

    auto cpKV = [&](const __nv_bfloat16* srcH, const __nv_bfloat16* srcL, int ch, int s) {
        uint32_t base = sb + (uint32_t)(4352 + s * 17408) * 2;
        int row = t >> 1, c0 = (t & 1) * 64;
        const int gsrc = (kbase + ch * 64 + row) * DD + c0;
#pragma unroll
        for (int i = 0; i < 8; i++) {
            uint32_t d = base + (uint32_t)(row * 136 + c0 + i * 8) * 2;
            CPA16(d,         srcH + gsrc + i * 8);
            CPA16(d + 17408, srcL + gsrc + i * 8);
        }
    };

    // ---- group 1: Q + bias + K0 ; group 2: K1 ----
    {
        int row = t >> 3, c0 = (t & 7) * 16;
        const int gsrc = (nbase + row) * DD + c0;
#pragma unroll
        for (int i = 0; i < 2; i++) {
            uint32_t d = sb + (uint32_t)(row * 136 + c0 + i * 8) * 2;
            CPA16(d,        g_qh + gsrc + i * 8);
            CPA16(d + 4352, g_ql + gsrc + i * 8);
        }
        int bcol = (t & 7) * 32;
        const float* bsrc = g_bias + (nbase + row) * NPG + bcol;
        uint32_t bdst = sb + 95232 + (uint32_t)(row * 260 + bcol) * 4;
#pragma unroll
        for (int i = 0; i < 8; i++)
            CPA16(bdst + i * 16, bsrc + i * 4);
    }
    cpKV(g_kh, g_kl, 0, 0); CP_COMMIT();
    cpKV(g_kh, g_kl, 1, 1); CP_COMMIT();

    const uint32_t aQh = sb + (uint32_t)(((lane & 15) * 136 + (lane >> 4) * 8)) * 2;
    const uint32_t aQl = aQh + 4352;
    const uint32_t boffK = (uint32_t)(((lane & 7) * 136 + (lane >> 3) * 8)) * 2;

    const int gr = lane >> 2;
    const int tq = lane & 3;

    // ---- Phase 1: S = Q K^T (registers), pipelined K chunks ----
    float s[8][4];
#pragma unroll
    for (int ti = 0; ti < 8; ti++)
#pragma unroll
        for (int j = 0; j < 4; j++) s[ti][j] = 0.f;

    for (int ch = 0; ch < 4; ch++) {
        CP_WAIT1();
        __syncthreads();
        const int st = ch & 1;
        const uint32_t bKh = sb + (uint32_t)(4352 + st * 17408) * 2 + boffK;
        const uint32_t bKl = bKh + 17408;

#pragma unroll
        for (int kp = 0; kp < 4; kp++) {
            uint32_t ah0[4], ah1[4], al0[4], al1[4];
            ldsm_x4(aQh + kp * 64,      ah0);
            ldsm_x4(aQh + kp * 64 + 32, ah1);
            ldsm_x4(aQl + kp * 64,      al0);
            ldsm_x4(aQl + kp * 64 + 32, al1);
#pragma unroll
            for (int nt = 0; nt < 2; nt++) {
                int ti = ch * 2 + nt;
                uint32_t bofs = (uint32_t)(((wn * 16 + nt * 8) * 136) * 2) + kp * 64;
                uint32_t bh[4], bl[4];
                ldsm_x4(bKh + bofs, bh);
                ldsm_x4(bKl + bofs, bl);
                mma_bf16(s[ti], ah0, bh);
                mma_bf16(s[ti], ah0, bl);
                mma_bf16(s[ti], al0, bh);
                mma_bf16(s[ti], ah1, bh + 2);
                mma_bf16(s[ti], ah1, bl + 2);
                mma_bf16(s[ti], al1, bh + 2);
            }
        }
        __syncthreads();
        if (ch < 2) cpKV(g_kh, g_kl, ch + 2, st);
        else        cpKV(g_vh, g_vl, ch - 2, st);
        CP_COMMIT();
    }

    // ---- bias (smem) + row max ----
    float mx0 = -1e30f, mx1 = -1e30f;
#pragma unroll
    for (int ti = 0; ti < 8; ti++) {
        int col = (ti >> 1) * 64 + wn * 16 + (ti & 1) * 8 + tq * 2;
        float2 b0 = *(const float2*)(sBiasF + gr * 260 + col);
        float2 b1 = *(const float2*)(sBiasF + (gr + 8) * 260 + col);
        s[ti][0] = s[ti][0] * RSCALE + b0.x;
        s[ti][1] = s[ti][1] * RSCALE + b0.y;
        s[ti][2] = s[ti][2] * RSCALE + b1.x;
        s[ti][3] = s[ti][3] * RSCALE + b1.y;
        mx0 = fmaxf(mx0, fmaxf(s[ti][0], s[ti][1]));
        mx1 = fmaxf(mx1, fmaxf(s[ti][2], s[ti][3]));
    }
    mx0 = fmaxf(mx0, __shfl_xor_sync(0xffffffffu, mx0, 1));
    mx0 = fmaxf(mx0, __shfl_xor_sync(0xffffffffu, mx0, 2));
    mx1 = fmaxf(mx1, __shfl_xor_sync(0xffffffffu, mx1, 1));
    mx1 = fmaxf(mx1, __shfl_xor_sync(0xffffffffu, mx1, 2));
    if (tq == 0) {
        sMax[gr * 4 + wn]       = mx0;
        sMax[(gr + 8) * 4 + wn] = mx1;
    }
    __syncthreads();
    mx0 = fmaxf(fmaxf(sMax[gr * 4 + 0], sMax[gr * 4 + 1]),
                fmaxf(sMax[gr * 4 + 2], sMax[gr * 4 + 3]));
    mx1 = fmaxf(fmaxf(sMax[(gr + 8) * 4 + 0], sMax[(gr + 8) * 4 + 1]),
                fmaxf(sMax[(gr + 8) * 4 + 2], sMax[(gr + 8) * 4 + 3]));

    // ---- exp + sum; P -> smem split-bf16 ----
    float sum0 = 0.f, sum1 = 0.f;
#pragma unroll
    for (int ti = 0; ti < 8; ti++) {
        int col = (ti >> 1) * 64 + wn * 16 + (ti & 1) * 8 + tq * 2;
        float e0 = __expf(s[ti][0] - mx0);
        float e1 = __expf(s[ti][1] - mx0);
        float e2 = __expf(s[ti][2] - mx1);
        float e3 = __expf(s[ti][3] - mx1);
        sum0 += e0 + e1;
        sum1 += e2 + e3;
        uint32_t lo0, lo1;
        uint32_t hi0 = split_pack(e0, e1, &lo0);
        uint32_t hi1 = split_pack(e2, e3, &lo1);
        *(uint32_t*)(sPh + gr * 264 + col)       = hi0;
        *(uint32_t*)(sPl + gr * 264 + col)       = lo0;
        *(uint32_t*)(sPh + (gr + 8) * 264 + col) = hi1;
        *(uint32_t*)(sPl + (gr + 8) * 264 + col) = lo1;
    }
    sum0 += __shfl_xor_sync(0xffffffffu, sum0, 1);
    sum0 += __shfl_xor_sync(0xffffffffu, sum0, 2);
    sum1 += __shfl_xor_sync(0xffffffffu, sum1, 1);
    sum1 += __shfl_xor_sync(0xffffffffu, sum1, 2);
    if (tq == 0) {
        sSum[gr * 4 + wn]       = sum0;
        sSum[(gr + 8) * 4 + wn] = sum1;
    }

    // ---- Phase 2: O = P V, pipelined V chunks ----
    float o[4][4];
#pragma unroll
    for (int nt = 0; nt < 4; nt++)
#pragma unroll
        for (int j = 0; j < 4; j++) o[nt][j] = 0.f;

    const uint32_t aPh = sb + (uint32_t)(39168 * 2) +
        (uint32_t)(((lane & 15) * 264 + (lane >> 4) * 8)) * 2;
    const uint32_t aPl = aPh + 8448;
    const uint32_t boffV =
        (uint32_t)((((lane & 7) + (lane & 8)) * 136 + ((lane >> 4) & 1) * 8)) * 2;

    for (int ch = 0; ch < 4; ch++) {
        if (ch == 3) { CP_WAIT0(); } else { CP_WAIT1(); }
        __syncthreads();
        const int st = ch & 1;
        const uint32_t bVh = sb + (uint32_t)(4352 + st * 17408) * 2 + boffV;
        const uint32_t bVl = bVh + 17408;

#pragma unroll
        for (int kt = 0; kt < 4; kt++) {
            uint32_t ph[4], pl[4];
            ldsm_x4(aPh + (ch * 64 + kt * 16) * 2, ph);
            ldsm_x4(aPl + (ch * 64 + kt * 16) * 2, pl);
#pragma unroll
            for (int np = 0; np < 2; np++) {
                uint32_t vofs = (uint32_t)((kt * 16 * 136 + wn * 32 + np * 16) * 2);
                uint32_t vh[4], vl[4];
                ldsm_x4_t(bVh + vofs, vh);
                ldsm_x4_t(bVl + vofs, vl);
                mma_bf16(o[np * 2],     ph, vh);
                mma_bf16(o[np * 2],     ph, vl);
                mma_bf16(o[np * 2],     pl, vh);
                mma_bf16(o[np * 2 + 1], ph, vh + 2);
                mma_bf16(o[np * 2 + 1], ph, vl + 2);
                mma_bf16(o[np * 2 + 1], pl, vh + 2);
            }
        }
        __syncthreads();
        if (ch < 2) { cpKV(g_vh, g_vl, ch + 2, st); CP_COMMIT(); }
    }

    // ---- epilogue: normalize, store ----
    float r0inv = 1.0f / (sSum[gr * 4 + 0] + sSum[gr * 4 + 1] +
                          sSum[gr * 4 + 2] + sSum[gr * 4 + 3]);
    float r1inv = 1.0f / (sSum[(gr + 8) * 4 + 0] + sSum[(gr + 8) * 4 + 1] +
                          sSum[(gr + 8) * 4 + 2] + sSum[(gr + 8) * 4 + 3]);
    int row0 = nbase + gr;
#pragma unroll
    for (int nt = 0; nt < 4; nt++) {
        int col = wn * 32 + nt * 8 + tq * 2;
        *(float2*)(out + row0 * DD + col) =
            make_float2(o[nt][0] * r0inv, o[nt][1] * r0inv);
        *(float2*)(out + (row0 + 8) * DD + col) =
            make_float2(o[nt][2] * r1inv, o[nt][3] * r1inv);
    }
}

// =====================================================================
extern "C" void kernel_launch(void* const* d_in, const int* in_sizes, int n_in,
                              void* d_out, int out_size)
{
    const float* x    = (const float*)d_in[0];
    const float* bmat = (const float*)d_in[1];
    const float* cmat = (const float*)d_in[2];
    // d_in[3] = ptr (uniform graph layout: NPG = 256; unused)
    const int*   mask = (const int*)d_in[4];
    const float* Wq   = (const float*)d_in[5];
    const float* bq   = (const float*)d_in[6];
    const float* Wk   = (const float*)d_in[7];
    const float* bk   = (const float*)d_in[8];
    const float* Wv   = (const float*)d_in[9];
    const float* bv   = (const float*)d_in[10];
    float* out = (float*)d_out;

    cudaFuncSetAttribute(qkv_mma_kernel, cudaFuncAttributeMaxDynamicSharedMemorySize,
                         QKV_SMEM_BYTES);
    cudaFuncSetAttribute(attn_mma_kernel, cudaFuncAttributeMaxDynamicSharedMemorySize,
                         ATTN_SMEM);

    prep_bias_kernel<<<(NN * NPG / 4) / 256, 256>>>(bmat, cmat, mask);
    convert_x_kernel<<<(NN * DIN / 4) / 256, 256>>>(x);
    convert_w_kernel<<<(3 * DD * DIN / 4) / 256, 256>>>(Wq, Wk, Wv);
    qkv_mma_kernel<<<dim3(128, 3), 128, QKV_SMEM_BYTES>>>(bq, bk, bv);
    attn_mma_kernel<<<dim3(16, 16), 128, ATTN_SMEM>>>(out);
}